// round 12
// baseline (speedup 1.0000x reference)
#include <cuda_runtime.h>
#include <cuda_bf16.h>
#include <math.h>
#include <stdint.h>

#define NNODES 50000
#define TT 8
#define HH 128
#define COUT 32
#define EDGES 800000
#define MROWS 400000

// ======================= scratch (device globals) ============================
__device__ int   g_is64;
__device__ int   g_src[EDGES];
__device__ int   g_dst[EDGES];
__device__ int   g_cnt[NNODES];
__device__ int   g_off[NNODES];
__device__ int   g_cur[NNODES];
__device__ int   g_adj[EDGES];
__device__ float g_AX [(size_t)MROWS*64];      // [m=(n*8+t), 64] = [agg/deg | x]
__device__ float g_Wcat[HH*64];                // [128, 64] = [Wl | Wr]
__device__ float g_Wh [96*HH];                 // [96, 128] = [W_rec ; W_c1]
__device__ float g_bh [96];
__device__ float g_GX [(size_t)MROWS*3*HH];    // [m, 384]
__device__ float g_H  [(size_t)NNODES*HH];     // [n, 128]
__device__ float g_HS [(size_t)MROWS*HH];      // [m, 128]

// ======================= helpers =============================================
// split two fp32 into packed bf16x2 hi + lo (lo = rounded residual)
__device__ __forceinline__ void bsplit2(float v0, float v1, uint32_t& hi, uint32_t& lo) {
    __nv_bfloat16 h0 = __float2bfloat16_rn(v0);
    __nv_bfloat16 h1 = __float2bfloat16_rn(v1);
    __nv_bfloat16 l0 = __float2bfloat16_rn(v0 - __bfloat162float(h0));
    __nv_bfloat16 l1 = __float2bfloat16_rn(v1 - __bfloat162float(h1));
    hi = ((uint32_t)__bfloat16_as_ushort(h1) << 16) | __bfloat16_as_ushort(h0);
    lo = ((uint32_t)__bfloat16_as_ushort(l1) << 16) | __bfloat16_as_ushort(l0);
}
#define MMA_BF16(C, Af, Bf) \
    asm volatile( \
        "mma.sync.aligned.m16n8k16.row.col.f32.bf16.bf16.f32 " \
        "{%0,%1,%2,%3}, {%4,%5,%6,%7}, {%8,%9}, {%0,%1,%2,%3};" \
        : "+f"((C)[0]), "+f"((C)[1]), "+f"((C)[2]), "+f"((C)[3]) \
        : "r"((Af)[0]), "r"((Af)[1]), "r"((Af)[2]), "r"((Af)[3]), \
          "r"((Bf)[0]), "r"((Bf)[1]))
#define CP_ASYNC16(dst, src, sz) \
    asm volatile("cp.async.ca.shared.global [%0], [%1], 16, %2;" \
                 :: "r"(dst), "l"(src), "r"(sz))
#define CP_COMMIT() asm volatile("cp.async.commit_group;" ::: "memory")
#define CP_WAIT1()  asm volatile("cp.async.wait_group 1;" ::: "memory")
#define CP_WAIT0()  asm volatile("cp.async.wait_group 0;" ::: "memory")
__device__ __forceinline__ float sigmoidf_(float v) { return 1.f / (1.f + expf(-v)); }

// load A-fragment (rows r0,r0+8; k pair base ka) from smem with stride S
#define LOAD_AFRAG(afh, afl, P, S, r0, ka) do { \
    float2 _p0 = *(const float2*)&(P)[ (r0)    *(S) + (ka)    ]; \
    float2 _p1 = *(const float2*)&(P)[((r0)+8) *(S) + (ka)    ]; \
    float2 _p2 = *(const float2*)&(P)[ (r0)    *(S) + (ka) + 8]; \
    float2 _p3 = *(const float2*)&(P)[((r0)+8) *(S) + (ka) + 8]; \
    bsplit2(_p0.x, _p0.y, (afh)[0], (afl)[0]); \
    bsplit2(_p1.x, _p1.y, (afh)[1], (afl)[1]); \
    bsplit2(_p2.x, _p2.y, (afh)[2], (afl)[2]); \
    bsplit2(_p3.x, _p3.y, (afh)[3], (afl)[3]); \
} while (0)
#define LOAD_BFRAG(bfh, bfl, P, S, cb, kb) do { \
    float2 _q0 = *(const float2*)&(P)[(cb)*(S) + (kb)    ]; \
    float2 _q1 = *(const float2*)&(P)[(cb)*(S) + (kb) + 8]; \
    bsplit2(_q0.x, _q0.y, (bfh)[0], (bfl)[0]); \
    bsplit2(_q1.x, _q1.y, (bfh)[1], (bfl)[1]); \
} while (0)

// ======================= edge dtype detect + convert =========================
__global__ void detect_kernel(const void* ei) {
    const unsigned long long* p = (const unsigned long long*)ei;
    int is64 = 1;
    for (int i = 0; i < 1024; i++)
        if ((p[i] >> 32) != 0ull) { is64 = 0; break; }
    g_is64 = is64;
}
__global__ void convert_kernel(const void* ei) {
    int e = blockIdx.x * blockDim.x + threadIdx.x;
    if (e >= EDGES) return;
    int s, d;
    if (g_is64) {
        const long long* p = (const long long*)ei;
        s = (int)p[e]; d = (int)p[EDGES + e];
    } else {
        const int* p = (const int*)ei;
        s = p[e]; d = p[EDGES + e];
    }
    s = min(max(s, 0), NNODES - 1);
    d = min(max(d, 0), NNODES - 1);
    g_src[e] = s;
    g_dst[e] = d;
}

// ======================= graph prep ==========================================
__global__ void zero_kernel() {
    int idx = blockIdx.x * blockDim.x + threadIdx.x;
    int stride = gridDim.x * blockDim.x;
    for (int i = idx; i < NNODES; i += stride) g_cnt[i] = 0;
}
__global__ void count_kernel() {
    int e = blockIdx.x * blockDim.x + threadIdx.x;
    if (e < EDGES) atomicAdd(&g_cnt[g_dst[e]], 1);
}
__global__ void scan_kernel() {
    __shared__ int partial[1024];
    const int CH = (NNODES + 1023) / 1024;
    int t = threadIdx.x;
    int begin = t * CH;
    int end   = min(begin + CH, NNODES);
    int s = 0;
    for (int i = begin; i < end; i++) s += g_cnt[i];
    partial[t] = s;
    __syncthreads();
    #pragma unroll
    for (int d = 1; d < 1024; d <<= 1) {
        int v = (t >= d) ? partial[t - d] : 0;
        __syncthreads();
        partial[t] += v;
        __syncthreads();
    }
    int off = partial[t] - s;
    for (int i = begin; i < end; i++) {
        g_off[i] = off;
        g_cur[i] = off;
        off += g_cnt[i];
    }
}
__global__ void fill_kernel() {
    int e = blockIdx.x * blockDim.x + threadIdx.x;
    if (e >= EDGES) return;
    int pos = atomicAdd(&g_cur[g_dst[e]], 1);
    g_adj[pos] = g_src[e];
}
__global__ void __launch_bounds__(256) gather_kernel(const float* __restrict__ x) {
    int n   = blockIdx.x;
    int idx = threadIdx.x;
    int beg = g_off[n];
    int cnt = g_cnt[n];
    float s = 0.f;
    for (int p = beg; p < beg + cnt; p++) {
        int src = g_adj[p];
        s += x[(size_t)src * 256 + idx];
    }
    float dg = fmaxf((float)cnt, 1.f);
    int t = idx >> 5, c = idx & 31;
    size_t m = (size_t)n * 8 + t;
    g_AX[m * 64 + c]      = s / dg;
    g_AX[m * 64 + 32 + c] = x[(size_t)n * 256 + idx];
}
__global__ void wcat_kernel(const float* __restrict__ Wl, const float* __restrict__ Wr) {
    int idx = blockIdx.x * blockDim.x + threadIdx.x;
    if (idx >= HH*64) return;
    int j = idx >> 6, c = idx & 63;
    g_Wcat[idx] = (c < 32) ? Wl[j*32 + c] : Wr[j*32 + (c-32)];
}
__global__ void headcat_kernel(const float* __restrict__ W_rec, const float* __restrict__ b_rec,
                               const float* __restrict__ W_c1,  const float* __restrict__ b_c1) {
    int idx = blockIdx.x * blockDim.x + threadIdx.x;
    if (idx < 96*HH) {
        int r = idx >> 7, k = idx & 127;
        g_Wh[idx] = (r < 32) ? W_rec[r*128 + k] : W_c1[(r-32)*128 + k];
    }
    if (idx < 96) g_bh[idx] = (idx < 32) ? b_rec[idx] : b_c1[idx - 32];
}

// ======================= t=0 GRU (H0 = 0 => gh = b_hh) =======================
__global__ void gru0_kernel(const float* __restrict__ b_hh) {
    int idx = blockIdx.x * blockDim.x + threadIdx.x;
    if (idx >= NNODES*HH) return;
    int i = idx >> 7, j = idx & 127;
    size_t m = (size_t)i*8;
    float r  = sigmoidf_(g_GX[m*384 + j]       + b_hh[j]);
    float z  = sigmoidf_(g_GX[m*384 + 128 + j] + b_hh[128 + j]);
    float nn = tanhf(g_GX[m*384 + 256 + j] + r * b_hh[256 + j]);
    float hn = (1.f - z)*nn;
    g_H[idx]       = hn;
    g_HS[m*HH + j] = hn;
}

// ======================= common tiling constants =============================
#define SROW 36
#define SMAT (128*SROW)
#define GSMEM (2*2*SMAT*4)             /* 73728 B: 2 stages x (A+B) */
#define C1S   72                       /* head cls smem stride */

// ======================= fused SP+GX kernel (3xBF16) =========================
#define SPX_ST  132
#define SPX_OFF (4*SMAT)
#define SPX_SMEM ((4*SMAT + 128*SPX_ST)*4)   /* 141312 B */

__global__ void __launch_bounds__(512, 1) spgx_kernel(
    const float* __restrict__ W_ih,
    const float* __restrict__ bl,
    const float* __restrict__ b_ih)
{
    extern __shared__ float smem[];
    uint32_t smem_b;
    asm("{ .reg .u64 t; cvta.to.shared.u64 t, %1; cvt.u32.u64 %0, t; }"
        : "=r"(smem_b) : "l"(smem));

    const int tid  = threadIdx.x;
    const int lane = tid & 31;
    const int w    = tid >> 5;
    const int gid  = lane >> 2;
    const int tig  = lane & 3;
    const int wm   = w >> 2;
    const int wn   = w & 3;
    const int bm   = blockIdx.x * 128;
    float* SPs = smem + SPX_OFF;

    float acc[2][4][4];
    #pragma unroll
    for (int i = 0; i < 2; i++)
        #pragma unroll
        for (int j = 0; j < 4; j++)
            #pragma unroll
            for (int k = 0; k < 4; k++) acc[i][j][k] = 0.f;

    // ---------------- phase 1: SP = relu(AX @ Wcat^T + bl) ----------------
    auto issue_copy1 = [&](int kc) {
        const uint32_t abase = smem_b + (uint32_t)((kc & 1) * 2 * SMAT) * 4u;
        const uint32_t bbase = abase + (uint32_t)SMAT * 4u;
        #pragma unroll
        for (int h = 0; h < 2; h++) {
            int i   = tid + h * 512;
            int row = i >> 3;
            int seg = i & 7;
            uint32_t soff = (uint32_t)(row * SROW + seg * 4) * 4u;
            CP_ASYNC16(abase + soff, g_AX + (size_t)(bm + row) * 64 + kc * 32 + seg * 4, 16);
            CP_ASYNC16(bbase + soff, g_Wcat + (size_t)row * 64 + kc * 32 + seg * 4, 16);
        }
        CP_COMMIT();
    };

    issue_copy1(0);
    for (int kc = 0; kc < 2; kc++) {
        if (kc == 0) { issue_copy1(1); CP_WAIT1(); } else { CP_WAIT0(); }
        __syncthreads();
        const float* Af = smem + (kc & 1) * 2 * SMAT;
        const float* Bf = Af + SMAT;
        #pragma unroll
        for (int ks = 0; ks < 2; ks++) {
            const int kk = ks*16 + tig*2;
            uint32_t afh[2][4], afl[2][4];
            #pragma unroll
            for (int mt = 0; mt < 2; mt++)
                LOAD_AFRAG(afh[mt], afl[mt], Af, SROW, wm*32 + mt*16 + gid, kk);
            #pragma unroll
            for (int nt = 0; nt < 4; nt++) {
                int cb = wn*32 + nt*8 + gid;
                uint32_t bfh[2], bfl[2];
                LOAD_BFRAG(bfh, bfl, Bf, SROW, cb, kk);
                #pragma unroll
                for (int mt = 0; mt < 2; mt++) {
                    MMA_BF16(acc[mt][nt], afh[mt], bfh);
                    MMA_BF16(acc[mt][nt], afh[mt], bfl);
                    MMA_BF16(acc[mt][nt], afl[mt], bfh);
                }
            }
        }
        __syncthreads();
    }
    // stage relu(SP) into smem
    #pragma unroll
    for (int mt = 0; mt < 2; mt++)
        #pragma unroll
        for (int nt = 0; nt < 4; nt++) {
            int col = wn*32 + nt*8 + 2*tig;
            #pragma unroll
            for (int half = 0; half < 2; half++) {
                int lrow = wm*32 + mt*16 + gid + half*8;
                SPs[lrow*SPX_ST + col]     = fmaxf(acc[mt][nt][half*2 + 0] + bl[col],     0.f);
                SPs[lrow*SPX_ST + col + 1] = fmaxf(acc[mt][nt][half*2 + 1] + bl[col + 1], 0.f);
            }
        }
    __syncthreads();

    // ---------------- phase 2: GX = SP @ W_ih^T + b_ih (3 N-subtiles) -------
    auto issue_copyB = [&](int idx) {   // idx = nt*4 + kc
        int nt = idx >> 2, kc = idx & 3;
        const uint32_t bbase = smem_b + (uint32_t)((idx & 1) * 2 * SMAT) * 4u;
        #pragma unroll
        for (int h = 0; h < 2; h++) {
            int i   = tid + h * 512;
            int row = i >> 3;
            int seg = i & 7;
            uint32_t soff = (uint32_t)(row * SROW + seg * 4) * 4u;
            CP_ASYNC16(bbase + soff, W_ih + (size_t)(nt*128 + row)*128 + kc*32 + seg*4, 16);
        }
        CP_COMMIT();
    };

    issue_copyB(0);
    for (int nt3 = 0; nt3 < 3; nt3++) {
        #pragma unroll
        for (int i = 0; i < 2; i++)
            #pragma unroll
            for (int j = 0; j < 4; j++)
                #pragma unroll
                for (int k = 0; k < 4; k++) acc[i][j][k] = 0.f;

        for (int kc = 0; kc < 4; kc++) {
            int idx = nt3*4 + kc;
            if (idx + 1 < 12) { issue_copyB(idx + 1); CP_WAIT1(); } else { CP_WAIT0(); }
            __syncthreads();
            const float* Bf = smem + (idx & 1) * 2 * SMAT;

            #pragma unroll
            for (int ks = 0; ks < 2; ks++) {
                const int ka = kc*32 + ks*16 + tig*2;   // SP column (full K)
                const int kb = ks*16 + tig*2;           // B chunk-local
                uint32_t afh[2][4], afl[2][4];
                #pragma unroll
                for (int mt = 0; mt < 2; mt++)
                    LOAD_AFRAG(afh[mt], afl[mt], SPs, SPX_ST, wm*32 + mt*16 + gid, ka);
                #pragma unroll
                for (int nt = 0; nt < 4; nt++) {
                    int cb = wn*32 + nt*8 + gid;
                    uint32_t bfh[2], bfl[2];
                    LOAD_BFRAG(bfh, bfl, Bf, SROW, cb, kb);
                    #pragma unroll
                    for (int mt = 0; mt < 2; mt++) {
                        MMA_BF16(acc[mt][nt], afh[mt], bfh);
                        MMA_BF16(acc[mt][nt], afh[mt], bfl);
                        MMA_BF16(acc[mt][nt], afl[mt], bfh);
                    }
                }
            }
            __syncthreads();
        }

        #pragma unroll
        for (int mt = 0; mt < 2; mt++)
            #pragma unroll
            for (int nt = 0; nt < 4; nt++) {
                int col = nt3*128 + wn*32 + nt*8 + 2*tig;
                #pragma unroll
                for (int half = 0; half < 2; half++) {
                    int row = bm + wm*32 + mt*16 + gid + half*8;
                    float2 o;
                    o.x = acc[mt][nt][half*2 + 0] + b_ih[col];
                    o.y = acc[mt][nt][half*2 + 1] + b_ih[col + 1];
                    *(float2*)(g_GX + (size_t)row*384 + col) = o;
                }
            }
    }
}

// ======================= head GEMM + fused cls (3xBF16) ======================
__global__ void __launch_bounds__(512, 1) head_kernel(
    const float* __restrict__ w2, const float* __restrict__ b2,
    float* __restrict__ recon, float* __restrict__ clsOut)
{
    extern __shared__ float smem[];
    uint32_t smem_b;
    asm("{ .reg .u64 t; cvta.to.shared.u64 t, %1; cvt.u32.u64 %0, t; }"
        : "=r"(smem_b) : "l"(smem));

    const int tid  = threadIdx.x;
    const int lane = tid & 31;
    const int w    = tid >> 5;
    const int gid  = lane >> 2;
    const int tig  = lane & 3;
    const int wm   = w >> 2;
    const int wn   = w & 3;
    const int bm   = blockIdx.x * 128;

    float acc[2][4][4];
    #pragma unroll
    for (int i = 0; i < 2; i++)
        #pragma unroll
        for (int j = 0; j < 4; j++)
            #pragma unroll
            for (int k = 0; k < 4; k++) acc[i][j][k] = 0.f;

    auto issue_copy = [&](int kc) {
        const uint32_t abase = smem_b + (uint32_t)((kc & 1) * 2 * SMAT) * 4u;
        const uint32_t bbase = abase + (uint32_t)SMAT * 4u;
        #pragma unroll
        for (int h = 0; h < 2; h++) {
            int i   = tid + h * 512;
            int row = i >> 3;
            int seg = i & 7;
            uint32_t soff = (uint32_t)(row * SROW + seg * 4) * 4u;
            CP_ASYNC16(abase + soff, g_HS + (size_t)(bm + row)*128 + kc*32 + seg*4, 16);
            CP_ASYNC16(bbase + soff, g_Wh + (size_t)min(row, 95)*128 + kc*32 + seg*4,
                       (row < 96) ? 16 : 0);
        }
        CP_COMMIT();
    };

    issue_copy(0);
    for (int kc = 0; kc < 4; kc++) {
        if (kc + 1 < 4) { issue_copy(kc + 1); CP_WAIT1(); } else { CP_WAIT0(); }
        __syncthreads();
        const float* Af = smem + (kc & 1) * 2 * SMAT;
        const float* Bf = Af + SMAT;
        #pragma unroll
        for (int ks = 0; ks < 2; ks++) {
            const int kk = ks*16 + tig*2;
            uint32_t afh[2][4], afl[2][4];
            #pragma unroll
            for (int mt = 0; mt < 2; mt++)
                LOAD_AFRAG(afh[mt], afl[mt], Af, SROW, wm*32 + mt*16 + gid, kk);
            #pragma unroll
            for (int nt = 0; nt < 4; nt++) {
                int cb = wn*32 + nt*8 + gid;
                uint32_t bfh[2], bfl[2];
                LOAD_BFRAG(bfh, bfl, Bf, SROW, cb, kk);
                #pragma unroll
                for (int mt = 0; mt < 2; mt++) {
                    MMA_BF16(acc[mt][nt], afh[mt], bfh);
                    MMA_BF16(acc[mt][nt], afh[mt], bfl);
                    MMA_BF16(acc[mt][nt], afl[mt], bfh);
                }
            }
        }
        __syncthreads();
    }

    #pragma unroll
    for (int mt = 0; mt < 2; mt++)
        #pragma unroll
        for (int nt = 0; nt < 4; nt++) {
            int col = wn*32 + nt*8 + 2*tig;
            if (col >= 96) continue;
            #pragma unroll
            for (int half = 0; half < 2; half++) {
                int row = bm + wm*32 + mt*16 + gid + half*8;
                float2 o;
                o.x = acc[mt][nt][half*2 + 0] + g_bh[col];
                o.y = acc[mt][nt][half*2 + 1] + g_bh[col + 1];
                if (col < 32) {
                    *(float2*)(recon + (size_t)row*32 + col) = o;
                } else {
                    int lrow = row - bm;
                    smem[lrow*C1S + col - 32]     = fmaxf(o.x, 0.f);
                    smem[lrow*C1S + col - 32 + 1] = fmaxf(o.y, 0.f);
                }
            }
        }
    __syncthreads();
    #pragma unroll
    for (int rr = 0; rr < 8; rr++) {
        int lrow = w*8 + rr;
        float s = smem[lrow*C1S + lane]      * w2[lane]
                + smem[lrow*C1S + 32 + lane] * w2[32 + lane];
        #pragma unroll
        for (int o = 16; o; o >>= 1) s += __shfl_xor_sync(0xffffffffu, s, o);
        if (lane == 0) clsOut[bm + lrow] = sigmoidf_(s + b2[0]);
    }
}

// ======================= fused GH GEMM + register GRU (3xBF16, t>=1) =========
#define GH_ASZ  (64*SROW)
#define GH_BSZ  (384*SROW)
#define GH_STG  (GH_ASZ + GH_BSZ)
#define GH_SMEM (2*GH_STG*4)

__global__ void __launch_bounds__(512, 1) ghgru_kernel(
    int t,
    const float* __restrict__ W_hh,
    const float* __restrict__ b_hh)
{
    extern __shared__ float smem[];
    uint32_t smem_b;
    asm("{ .reg .u64 t; cvta.to.shared.u64 t, %1; cvt.u32.u64 %0, t; }"
        : "=r"(smem_b) : "l"(smem));

    const int tid  = threadIdx.x;
    const int lane = tid & 31;
    const int w    = tid >> 5;
    const int gid  = lane >> 2;
    const int tig  = lane & 3;
    const int wm   = w >> 2;
    const int wn   = w & 3;
    const int bm   = blockIdx.x * 64;

    float acc[3][4][4];
    #pragma unroll
    for (int g = 0; g < 3; g++)
        #pragma unroll
        for (int j = 0; j < 4; j++)
            #pragma unroll
            for (int k = 0; k < 4; k++) acc[g][j][k] = 0.f;

    auto issue_copy = [&](int kc) {
        const int s = kc & 1;
        const uint32_t abase = smem_b + (uint32_t)(s * GH_STG) * 4u;
        const uint32_t bbase = abase + (uint32_t)GH_ASZ * 4u;
        {
            int row = tid >> 3;
            int seg = tid & 7;
            uint32_t soff = (uint32_t)(row * SROW + seg * 4) * 4u;
            int grow = bm + row;
            CP_ASYNC16(abase + soff,
                       g_H + (size_t)min(grow, NNODES - 1) * HH + kc * 32 + seg * 4,
                       (grow < NNODES) ? 16 : 0);
        }
        #pragma unroll
        for (int h = 0; h < 6; h++) {
            int i   = tid + h * 512;
            int row = i >> 3;
            int seg = i & 7;
            uint32_t soff = (uint32_t)(row * SROW + seg * 4) * 4u;
            CP_ASYNC16(bbase + soff, W_hh + (size_t)row * HH + kc * 32 + seg * 4, 16);
        }
        CP_COMMIT();
    };

    issue_copy(0);
    for (int kc = 0; kc < 4; kc++) {
        if (kc + 1 < 4) { issue_copy(kc + 1); CP_WAIT1(); } else { CP_WAIT0(); }
        __syncthreads();
        const float* Af = smem + (kc & 1) * GH_STG;
        const float* Bf = Af + GH_ASZ;
        #pragma unroll
        for (int ks = 0; ks < 2; ks++) {
            const int kk = ks*16 + tig*2;
            uint32_t afh[4], afl[4];
            LOAD_AFRAG(afh, afl, Af, SROW, wm*16 + gid, kk);
            #pragma unroll
            for (int g = 0; g < 3; g++) {
                #pragma unroll
                for (int nt = 0; nt < 4; nt++) {
                    int cb = g*128 + wn*32 + nt*8 + gid;
                    uint32_t bfh[2], bfl[2];
                    LOAD_BFRAG(bfh, bfl, Bf, SROW, cb, kk);
                    MMA_BF16(acc[g][nt], afh, bfh);
                    MMA_BF16(acc[g][nt], afh, bfl);
                    MMA_BF16(acc[g][nt], afl, bfh);
                }
            }
        }
        __syncthreads();
    }

    #pragma unroll
    for (int nt = 0; nt < 4; nt++) {
        int col = wn*32 + nt*8 + 2*tig;
        float2 bhr = *(const float2*)(b_hh + col);
        float2 bhz = *(const float2*)(b_hh + 128 + col);
        float2 bhn = *(const float2*)(b_hh + 256 + col);
        #pragma unroll
        for (int half = 0; half < 2; half++) {
            int node = bm + wm*16 + gid + half*8;
            if (node >= NNODES) continue;
            size_t m = (size_t)node*8 + t;
            float2 gxr = *(const float2*)(g_GX + m*384 + col);
            float2 gxz = *(const float2*)(g_GX + m*384 + 128 + col);
            float2 gxn = *(const float2*)(g_GX + m*384 + 256 + col);
            float2 h   = *(const float2*)(g_H + (size_t)node*HH + col);
            float ghr0 = acc[0][nt][half*2+0] + bhr.x, ghr1 = acc[0][nt][half*2+1] + bhr.y;
            float ghz0 = acc[1][nt][half*2+0] + bhz.x, ghz1 = acc[1][nt][half*2+1] + bhz.y;
            float ghn0 = acc[2][nt][half*2+0] + bhn.x, ghn1 = acc[2][nt][half*2+1] + bhn.y;
            float r0 = sigmoidf_(gxr.x + ghr0), r1 = sigmoidf_(gxr.y + ghr1);
            float z0 = sigmoidf_(gxz.x + ghz0), z1 = sigmoidf_(gxz.y + ghz1);
            float n0 = tanhf(gxn.x + r0*ghn0),  n1 = tanhf(gxn.y + r1*ghn1);
            float2 hn;
            hn.x = (1.f - z0)*n0 + z0*h.x;
            hn.y = (1.f - z1)*n1 + z1*h.y;
            *(float2*)(g_H  + (size_t)node*HH + col) = hn;
            *(float2*)(g_HS + m*HH + col)            = hn;
        }
    }
}

// ======================= launch ==============================================
extern "C" void kernel_launch(void* const* d_in, const int* in_sizes, int n_in,
                              void* d_out, int out_size)
{
    const float* x     = (const float*)d_in[0];
    const void*  ei    = d_in[1];
    const float* Wl    = (const float*)d_in[2];
    const float* bl    = (const float*)d_in[3];
    const float* Wr    = (const float*)d_in[4];
    const float* W_ih  = (const float*)d_in[5];
    const float* b_ih  = (const float*)d_in[6];
    const float* W_hh  = (const float*)d_in[7];
    const float* b_hh  = (const float*)d_in[8];
    const float* W_rec = (const float*)d_in[9];
    const float* b_rec = (const float*)d_in[10];
    const float* W_c1  = (const float*)d_in[11];
    const float* b_c1  = (const float*)d_in[12];
    const float* W_c2  = (const float*)d_in[13];
    const float* b_c2  = (const float*)d_in[14];

    float* out      = (float*)d_out;
    float* outRecon = out;
    float* outCls   = out + (size_t)MROWS * COUT;

    cudaFuncSetAttribute(spgx_kernel,  cudaFuncAttributeMaxDynamicSharedMemorySize, SPX_SMEM);
    cudaFuncSetAttribute(head_kernel,  cudaFuncAttributeMaxDynamicSharedMemorySize, GSMEM);
    cudaFuncSetAttribute(ghgru_kernel, cudaFuncAttributeMaxDynamicSharedMemorySize, GH_SMEM);

    // graph prep
    detect_kernel<<<1, 1>>>(ei);
    convert_kernel<<<(EDGES + 255)/256, 256>>>(ei);
    zero_kernel<<<256, 256>>>();
    wcat_kernel<<<(HH*64 + 255)/256, 256>>>(Wl, Wr);
    headcat_kernel<<<(96*HH + 255)/256, 256>>>(W_rec, b_rec, W_c1, b_c1);
    count_kernel<<<(EDGES + 255)/256, 256>>>();
    scan_kernel<<<1, 1024>>>();
    fill_kernel<<<(EDGES + 255)/256, 256>>>();
    gather_kernel<<<NNODES, 256>>>(x);

    // fused SP+GX
    spgx_kernel<<<MROWS/128, 512, SPX_SMEM>>>(W_ih, bl, b_ih);

    // recurrence
    gru0_kernel<<<(NNODES*HH + 255)/256, 256>>>(b_hh);
    for (int t = 1; t < TT; t++)
        ghgru_kernel<<<(NNODES + 63)/64, 512, GH_SMEM>>>(t, W_hh, b_hh);

    // heads
    head_kernel<<<MROWS/128, 512, GSMEM>>>(W_c2, b_c2, outRecon, outCls);
}

// round 13
// speedup vs baseline: 1.4689x; 1.4689x over previous
#include <cuda_runtime.h>
#include <cuda_bf16.h>
#include <math.h>
#include <stdint.h>

#define NNODES 50000
#define TT 8
#define HH 128
#define COUT 32
#define EDGES 800000
#define MROWS 400000

typedef unsigned short ushort_t;

// ======================= scratch (device globals) ============================
__device__ int   g_is64;
__device__ int   g_src[EDGES];
__device__ int   g_dst[EDGES];
__device__ int   g_cnt[NNODES];
__device__ int   g_off[NNODES];
__device__ int   g_cur[NNODES];
__device__ int   g_adj[EDGES];
__device__ float g_GX [(size_t)MROWS*3*HH];    // [m, 384] fp32
__device__ float g_H  [(size_t)NNODES*HH];     // [n, 128] fp32 (GRU carry)
__device__ float g_bh [96];
// packed-bf16 hi/lo operand arrays
__device__ ushort_t g_AXhi[(size_t)MROWS*64],   g_AXlo[(size_t)MROWS*64];
__device__ ushort_t g_Wcathi[128*64],           g_Wcatlo[128*64];
__device__ ushort_t g_Wihhi[384*128],           g_Wihlo[384*128];
__device__ ushort_t g_Whhhi[384*128],           g_Whhlo[384*128];
__device__ ushort_t g_Whdhi[96*128],            g_Whdlo[96*128];
__device__ ushort_t g_Hhi [(size_t)NNODES*128], g_Hlo [(size_t)NNODES*128];
__device__ ushort_t g_HShi[(size_t)MROWS*128],  g_HSlo[(size_t)MROWS*128];

// ======================= helpers =============================================
__device__ __forceinline__ void bsplit1(float v, ushort_t& h, ushort_t& l) {
    __nv_bfloat16 hb = __float2bfloat16_rn(v);
    __nv_bfloat16 lb = __float2bfloat16_rn(v - __bfloat162float(hb));
    h = __bfloat16_as_ushort(hb); l = __bfloat16_as_ushort(lb);
}
__device__ __forceinline__ void bsplit2(float v0, float v1, uint32_t& hi, uint32_t& lo) {
    ushort_t h0, l0, h1, l1;
    bsplit1(v0, h0, l0); bsplit1(v1, h1, l1);
    hi = ((uint32_t)h1 << 16) | h0;
    lo = ((uint32_t)l1 << 16) | l0;
}
#define MMA_BF16(C, Af, Bf) \
    asm volatile( \
        "mma.sync.aligned.m16n8k16.row.col.f32.bf16.bf16.f32 " \
        "{%0,%1,%2,%3}, {%4,%5,%6,%7}, {%8,%9}, {%0,%1,%2,%3};" \
        : "+f"((C)[0]), "+f"((C)[1]), "+f"((C)[2]), "+f"((C)[3]) \
        : "r"((Af)[0]), "r"((Af)[1]), "r"((Af)[2]), "r"((Af)[3]), \
          "r"((Bf)[0]), "r"((Bf)[1]))
#define CP_ASYNC16(dst, src, sz) \
    asm volatile("cp.async.ca.shared.global [%0], [%1], 16, %2;" \
                 :: "r"(dst), "l"(src), "r"(sz))
#define CP_COMMIT() asm volatile("cp.async.commit_group;" ::: "memory")
#define CP_WAIT1()  asm volatile("cp.async.wait_group 1;" ::: "memory")
#define CP_WAIT0()  asm volatile("cp.async.wait_group 0;" ::: "memory")
__device__ __forceinline__ float sigmoidf_(float v) { return 1.f / (1.f + expf(-v)); }

// pure-load fragments from pre-split smem (ushort arrays, stride S2 ushorts)
#define LD_A4(af, P, S2, r0, kk) do { \
    (af)[0] = *(const uint32_t*)&(P)[ (r0)    *(S2) + (kk)    ]; \
    (af)[1] = *(const uint32_t*)&(P)[((r0)+8) *(S2) + (kk)    ]; \
    (af)[2] = *(const uint32_t*)&(P)[ (r0)    *(S2) + (kk) + 8]; \
    (af)[3] = *(const uint32_t*)&(P)[((r0)+8) *(S2) + (kk) + 8]; \
} while (0)
#define LD_B2(bf, P, S2, cb, kk) do { \
    (bf)[0] = *(const uint32_t*)&(P)[(cb)*(S2) + (kk)    ]; \
    (bf)[1] = *(const uint32_t*)&(P)[(cb)*(S2) + (kk) + 8]; \
} while (0)

// ======================= edge dtype detect + convert =========================
__global__ void detect_kernel(const void* ei) {
    const unsigned long long* p = (const unsigned long long*)ei;
    int is64 = 1;
    for (int i = 0; i < 1024; i++)
        if ((p[i] >> 32) != 0ull) { is64 = 0; break; }
    g_is64 = is64;
}
__global__ void convert_kernel(const void* ei) {
    int e = blockIdx.x * blockDim.x + threadIdx.x;
    if (e >= EDGES) return;
    int s, d;
    if (g_is64) {
        const long long* p = (const long long*)ei;
        s = (int)p[e]; d = (int)p[EDGES + e];
    } else {
        const int* p = (const int*)ei;
        s = p[e]; d = p[EDGES + e];
    }
    s = min(max(s, 0), NNODES - 1);
    d = min(max(d, 0), NNODES - 1);
    g_src[e] = s;
    g_dst[e] = d;
}

// ======================= graph prep ==========================================
__global__ void zero_kernel() {
    int idx = blockIdx.x * blockDim.x + threadIdx.x;
    int stride = gridDim.x * blockDim.x;
    for (int i = idx; i < NNODES; i += stride) g_cnt[i] = 0;
}
__global__ void count_kernel() {
    int e = blockIdx.x * blockDim.x + threadIdx.x;
    if (e < EDGES) atomicAdd(&g_cnt[g_dst[e]], 1);
}
__global__ void scan_kernel() {
    __shared__ int partial[1024];
    const int CH = (NNODES + 1023) / 1024;
    int t = threadIdx.x;
    int begin = t * CH;
    int end   = min(begin + CH, NNODES);
    int s = 0;
    for (int i = begin; i < end; i++) s += g_cnt[i];
    partial[t] = s;
    __syncthreads();
    #pragma unroll
    for (int d = 1; d < 1024; d <<= 1) {
        int v = (t >= d) ? partial[t - d] : 0;
        __syncthreads();
        partial[t] += v;
        __syncthreads();
    }
    int off = partial[t] - s;
    for (int i = begin; i < end; i++) {
        g_off[i] = off;
        g_cur[i] = off;
        off += g_cnt[i];
    }
}
__global__ void fill_kernel() {
    int e = blockIdx.x * blockDim.x + threadIdx.x;
    if (e >= EDGES) return;
    int pos = atomicAdd(&g_cur[g_dst[e]], 1);
    g_adj[pos] = g_src[e];
}
__global__ void __launch_bounds__(256) gather_kernel(const float* __restrict__ x) {
    int n   = blockIdx.x;
    int idx = threadIdx.x;
    int beg = g_off[n];
    int cnt = g_cnt[n];
    float s = 0.f;
    for (int p = beg; p < beg + cnt; p++) {
        int src = g_adj[p];
        s += x[(size_t)src * 256 + idx];
    }
    float dg = fmaxf((float)cnt, 1.f);
    int t = idx >> 5, c = idx & 31;
    size_t m = (size_t)n * 8 + t;
    ushort_t h, l;
    bsplit1(s / dg, h, l);
    g_AXhi[m*64 + c] = h;      g_AXlo[m*64 + c] = l;
    bsplit1(x[(size_t)n * 256 + idx], h, l);
    g_AXhi[m*64 + 32 + c] = h; g_AXlo[m*64 + 32 + c] = l;
}
// weight conversions
__global__ void wcat2_kernel(const float* __restrict__ Wl, const float* __restrict__ Wr) {
    int idx = blockIdx.x * blockDim.x + threadIdx.x;
    if (idx >= 128*64) return;
    int j = idx >> 6, c = idx & 63;
    float v = (c < 32) ? Wl[j*32 + c] : Wr[j*32 + (c-32)];
    bsplit1(v, g_Wcathi[idx], g_Wcatlo[idx]);
}
__global__ void wih2_kernel(const float* __restrict__ W_ih) {
    int idx = blockIdx.x * blockDim.x + threadIdx.x;
    if (idx >= 384*128) return;
    bsplit1(W_ih[idx], g_Wihhi[idx], g_Wihlo[idx]);
}
__global__ void whh2_kernel(const float* __restrict__ W_hh) {
    int idx = blockIdx.x * blockDim.x + threadIdx.x;
    if (idx >= 384*128) return;
    bsplit1(W_hh[idx], g_Whhhi[idx], g_Whhlo[idx]);
}
__global__ void whd2_kernel(const float* __restrict__ W_rec, const float* __restrict__ b_rec,
                            const float* __restrict__ W_c1,  const float* __restrict__ b_c1) {
    int idx = blockIdx.x * blockDim.x + threadIdx.x;
    if (idx < 96*128) {
        int r = idx >> 7, k = idx & 127;
        float v = (r < 32) ? W_rec[r*128 + k] : W_c1[(r-32)*128 + k];
        bsplit1(v, g_Whdhi[idx], g_Whdlo[idx]);
    }
    if (idx < 96) g_bh[idx] = (idx < 32) ? b_rec[idx] : b_c1[idx - 32];
}

// ======================= t=0 GRU (H0 = 0 => gh = b_hh) =======================
__global__ void gru0_kernel(const float* __restrict__ b_hh) {
    int idx = blockIdx.x * blockDim.x + threadIdx.x;
    if (idx >= NNODES*HH) return;
    int i = idx >> 7, j = idx & 127;
    size_t m = (size_t)i*8;
    float r  = sigmoidf_(g_GX[m*384 + j]       + b_hh[j]);
    float z  = sigmoidf_(g_GX[m*384 + 128 + j] + b_hh[128 + j]);
    float nn = tanhf(g_GX[m*384 + 256 + j] + r * b_hh[256 + j]);
    float hn = (1.f - z)*nn;
    g_H[idx] = hn;
    ushort_t h, l;
    bsplit1(hn, h, l);
    g_Hhi[idx]       = h; g_Hlo[idx]       = l;
    g_HShi[m*HH + j] = h; g_HSlo[m*HH + j] = l;
}

// ======================= tiling constants ====================================
#define SRW2 40                       /* ushort stride for 32-k chunk rows */
#define A128 (128*SRW2)               /* 5120 ushorts */
#define STG2 (4*A128)                 /* Ahi,Alo,Bhi,Blo = 20480 ushorts */
#define C1S  72

// ======================= fused SP+GX kernel ==================================
#define SPX_ST2  136
#define SPHI_OFF (2*STG2)                       /* 40960 ushorts */
#define SPLO_OFF (SPHI_OFF + 128*SPX_ST2)       /* 58368 */
#define SPX_SMEM ((SPLO_OFF + 128*SPX_ST2)*2)   /* 151552 B */

__global__ void __launch_bounds__(512, 1) spgx_kernel(
    const float* __restrict__ bl, const float* __restrict__ b_ih)
{
    extern __shared__ ushort_t smem[];
    uint32_t smem_b;
    asm("{ .reg .u64 t; cvta.to.shared.u64 t, %1; cvt.u32.u64 %0, t; }"
        : "=r"(smem_b) : "l"(smem));

    const int tid  = threadIdx.x;
    const int lane = tid & 31;
    const int w    = tid >> 5;
    const int gid  = lane >> 2;
    const int tig  = lane & 3;
    const int wm   = w >> 2;
    const int wn   = w & 3;
    const int bm   = blockIdx.x * 128;
    ushort_t* SPhi = smem + SPHI_OFF;
    ushort_t* SPlo = smem + SPLO_OFF;

    float acc[2][4][4];
    #pragma unroll
    for (int i = 0; i < 2; i++)
        #pragma unroll
        for (int j = 0; j < 4; j++)
            #pragma unroll
            for (int k = 0; k < 4; k++) acc[i][j][k] = 0.f;

    // ---------------- phase 1: SP = relu(AX @ Wcat^T + bl) ----------------
    // copies: per array 128 rows x 4 segs (16B = 8 ushorts) = 512 -> 1/thread
    auto issue_copy1 = [&](int kc) {
        const uint32_t sb = smem_b + (uint32_t)((kc & 1) * STG2) * 2u;
        int row = tid >> 2, seg = tid & 3;
        uint32_t soff = (uint32_t)(row * SRW2 + seg * 8) * 2u;
        size_t goff = (size_t)(bm + row) * 64 + kc * 32 + seg * 8;
        size_t woff = (size_t)row * 64 + kc * 32 + seg * 8;
        CP_ASYNC16(sb + soff,                    g_AXhi  + goff, 16);
        CP_ASYNC16(sb + (uint32_t)A128*2 + soff, g_AXlo  + goff, 16);
        CP_ASYNC16(sb + (uint32_t)(2*A128)*2 + soff, g_Wcathi + woff, 16);
        CP_ASYNC16(sb + (uint32_t)(3*A128)*2 + soff, g_Wcatlo + woff, 16);
        CP_COMMIT();
    };

    issue_copy1(0);
    for (int kc = 0; kc < 2; kc++) {
        if (kc == 0) { issue_copy1(1); CP_WAIT1(); } else { CP_WAIT0(); }
        __syncthreads();
        const ushort_t* Ahi = smem + (kc & 1) * STG2;
        const ushort_t* Alo = Ahi + A128;
        const ushort_t* Bhi = Ahi + 2*A128;
        const ushort_t* Blo = Ahi + 3*A128;
        #pragma unroll
        for (int ks = 0; ks < 2; ks++) {
            const int kk = ks*16 + tig*2;
            uint32_t afh[2][4], afl[2][4];
            #pragma unroll
            for (int mt = 0; mt < 2; mt++) {
                LD_A4(afh[mt], Ahi, SRW2, wm*32 + mt*16 + gid, kk);
                LD_A4(afl[mt], Alo, SRW2, wm*32 + mt*16 + gid, kk);
            }
            #pragma unroll
            for (int nt = 0; nt < 4; nt++) {
                int cb = wn*32 + nt*8 + gid;
                uint32_t bfh[2], bfl[2];
                LD_B2(bfh, Bhi, SRW2, cb, kk);
                LD_B2(bfl, Blo, SRW2, cb, kk);
                #pragma unroll
                for (int mt = 0; mt < 2; mt++) {
                    MMA_BF16(acc[mt][nt], afh[mt], bfh);
                    MMA_BF16(acc[mt][nt], afh[mt], bfl);
                    MMA_BF16(acc[mt][nt], afl[mt], bfh);
                }
            }
        }
        __syncthreads();
    }
    // stage relu(SP) split into smem hi/lo
    #pragma unroll
    for (int mt = 0; mt < 2; mt++)
        #pragma unroll
        for (int nt = 0; nt < 4; nt++) {
            int col = wn*32 + nt*8 + 2*tig;
            #pragma unroll
            for (int half = 0; half < 2; half++) {
                int lrow = wm*32 + mt*16 + gid + half*8;
                float vx = fmaxf(acc[mt][nt][half*2 + 0] + bl[col],     0.f);
                float vy = fmaxf(acc[mt][nt][half*2 + 1] + bl[col + 1], 0.f);
                uint32_t hi, lo;
                bsplit2(vx, vy, hi, lo);
                *(uint32_t*)&SPhi[lrow*SPX_ST2 + col] = hi;
                *(uint32_t*)&SPlo[lrow*SPX_ST2 + col] = lo;
            }
        }
    __syncthreads();

    // ---------------- phase 2: GX = SP @ W_ih^T + b_ih (3 N-subtiles) -------
    // B copies: 128 rows x 4 segs x 2 arrays = 1024 -> 2/thread
    auto issue_copyB = [&](int idx) {   // idx = nt*4 + kc
        int nt = idx >> 2, kc = idx & 3;
        const uint32_t sb = smem_b + (uint32_t)((idx & 1) * STG2) * 2u;
        int row = tid >> 2, seg = tid & 3;
        uint32_t soff = (uint32_t)(row * SRW2 + seg * 8) * 2u;
        size_t goff = (size_t)(nt*128 + row) * 128 + kc * 32 + seg * 8;
        CP_ASYNC16(sb + (uint32_t)(2*A128)*2 + soff, g_Wihhi + goff, 16);
        CP_ASYNC16(sb + (uint32_t)(3*A128)*2 + soff, g_Wihlo + goff, 16);
        CP_COMMIT();
    };

    issue_copyB(0);
    for (int nt3 = 0; nt3 < 3; nt3++) {
        #pragma unroll
        for (int i = 0; i < 2; i++)
            #pragma unroll
            for (int j = 0; j < 4; j++)
                #pragma unroll
                for (int k = 0; k < 4; k++) acc[i][j][k] = 0.f;

        for (int kc = 0; kc < 4; kc++) {
            int idx = nt3*4 + kc;
            if (idx + 1 < 12) { issue_copyB(idx + 1); CP_WAIT1(); } else { CP_WAIT0(); }
            __syncthreads();
            const ushort_t* Bhi = smem + (idx & 1) * STG2 + 2*A128;
            const ushort_t* Blo = Bhi + A128;

            #pragma unroll
            for (int ks = 0; ks < 2; ks++) {
                const int ka = kc*32 + ks*16 + tig*2;
                const int kb = ks*16 + tig*2;
                uint32_t afh[2][4], afl[2][4];
                #pragma unroll
                for (int mt = 0; mt < 2; mt++) {
                    LD_A4(afh[mt], SPhi, SPX_ST2, wm*32 + mt*16 + gid, ka);
                    LD_A4(afl[mt], SPlo, SPX_ST2, wm*32 + mt*16 + gid, ka);
                }
                #pragma unroll
                for (int nt = 0; nt < 4; nt++) {
                    int cb = wn*32 + nt*8 + gid;
                    uint32_t bfh[2], bfl[2];
                    LD_B2(bfh, Bhi, SRW2, cb, kb);
                    LD_B2(bfl, Blo, SRW2, cb, kb);
                    #pragma unroll
                    for (int mt = 0; mt < 2; mt++) {
                        MMA_BF16(acc[mt][nt], afh[mt], bfh);
                        MMA_BF16(acc[mt][nt], afh[mt], bfl);
                        MMA_BF16(acc[mt][nt], afl[mt], bfh);
                    }
                }
            }
            __syncthreads();
        }

        #pragma unroll
        for (int mt = 0; mt < 2; mt++)
            #pragma unroll
            for (int nt = 0; nt < 4; nt++) {
                int col = nt3*128 + wn*32 + nt*8 + 2*tig;
                #pragma unroll
                for (int half = 0; half < 2; half++) {
                    int row = bm + wm*32 + mt*16 + gid + half*8;
                    float2 o;
                    o.x = acc[mt][nt][half*2 + 0] + b_ih[col];
                    o.y = acc[mt][nt][half*2 + 1] + b_ih[col + 1];
                    *(float2*)(g_GX + (size_t)row*384 + col) = o;
                }
            }
    }
}

// ======================= head GEMM + fused cls ===============================
#define HEAD_SMEM (2*STG2*2)          /* 81920 B */
__global__ void __launch_bounds__(512, 1) head_kernel(
    const float* __restrict__ w2, const float* __restrict__ b2,
    float* __restrict__ recon, float* __restrict__ clsOut)
{
    extern __shared__ ushort_t smem[];
    uint32_t smem_b;
    asm("{ .reg .u64 t; cvta.to.shared.u64 t, %1; cvt.u32.u64 %0, t; }"
        : "=r"(smem_b) : "l"(smem));

    const int tid  = threadIdx.x;
    const int lane = tid & 31;
    const int w    = tid >> 5;
    const int gid  = lane >> 2;
    const int tig  = lane & 3;
    const int wm   = w >> 2;
    const int wn   = w & 3;
    const int bm   = blockIdx.x * 128;

    float acc[2][4][4];
    #pragma unroll
    for (int i = 0; i < 2; i++)
        #pragma unroll
        for (int j = 0; j < 4; j++)
            #pragma unroll
            for (int k = 0; k < 4; k++) acc[i][j][k] = 0.f;

    auto issue_copy = [&](int kc) {
        const uint32_t sb = smem_b + (uint32_t)((kc & 1) * STG2) * 2u;
        int row = tid >> 2, seg = tid & 3;
        uint32_t soff = (uint32_t)(row * SRW2 + seg * 8) * 2u;
        size_t aoff = (size_t)(bm + row) * 128 + kc * 32 + seg * 8;
        size_t woff = (size_t)min(row, 95) * 128 + kc * 32 + seg * 8;
        int wsz = (row < 96) ? 16 : 0;
        CP_ASYNC16(sb + soff,                        g_HShi + aoff, 16);
        CP_ASYNC16(sb + (uint32_t)A128*2 + soff,     g_HSlo + aoff, 16);
        CP_ASYNC16(sb + (uint32_t)(2*A128)*2 + soff, g_Whdhi + woff, wsz);
        CP_ASYNC16(sb + (uint32_t)(3*A128)*2 + soff, g_Whdlo + woff, wsz);
        CP_COMMIT();
    };

    issue_copy(0);
    for (int kc = 0; kc < 4; kc++) {
        if (kc + 1 < 4) { issue_copy(kc + 1); CP_WAIT1(); } else { CP_WAIT0(); }
        __syncthreads();
        const ushort_t* Ahi = smem + (kc & 1) * STG2;
        const ushort_t* Alo = Ahi + A128;
        const ushort_t* Bhi = Ahi + 2*A128;
        const ushort_t* Blo = Ahi + 3*A128;
        #pragma unroll
        for (int ks = 0; ks < 2; ks++) {
            const int kk = ks*16 + tig*2;
            uint32_t afh[2][4], afl[2][4];
            #pragma unroll
            for (int mt = 0; mt < 2; mt++) {
                LD_A4(afh[mt], Ahi, SRW2, wm*32 + mt*16 + gid, kk);
                LD_A4(afl[mt], Alo, SRW2, wm*32 + mt*16 + gid, kk);
            }
            #pragma unroll
            for (int nt = 0; nt < 4; nt++) {
                int cb = wn*32 + nt*8 + gid;
                uint32_t bfh[2], bfl[2];
                LD_B2(bfh, Bhi, SRW2, cb, kk);
                LD_B2(bfl, Blo, SRW2, cb, kk);
                #pragma unroll
                for (int mt = 0; mt < 2; mt++) {
                    MMA_BF16(acc[mt][nt], afh[mt], bfh);
                    MMA_BF16(acc[mt][nt], afh[mt], bfl);
                    MMA_BF16(acc[mt][nt], afl[mt], bfh);
                }
            }
        }
        __syncthreads();
    }

    float* c1s = (float*)smem;     // alias stage region (done with GEMM)
    #pragma unroll
    for (int mt = 0; mt < 2; mt++)
        #pragma unroll
        for (int nt = 0; nt < 4; nt++) {
            int col = wn*32 + nt*8 + 2*tig;
            if (col >= 96) continue;
            #pragma unroll
            for (int half = 0; half < 2; half++) {
                int row = bm + wm*32 + mt*16 + gid + half*8;
                float2 o;
                o.x = acc[mt][nt][half*2 + 0] + g_bh[col];
                o.y = acc[mt][nt][half*2 + 1] + g_bh[col + 1];
                if (col < 32) {
                    *(float2*)(recon + (size_t)row*32 + col) = o;
                } else {
                    int lrow = row - bm;
                    c1s[lrow*C1S + col - 32]     = fmaxf(o.x, 0.f);
                    c1s[lrow*C1S + col - 32 + 1] = fmaxf(o.y, 0.f);
                }
            }
        }
    __syncthreads();
    #pragma unroll
    for (int rr = 0; rr < 8; rr++) {
        int lrow = w*8 + rr;
        float s = c1s[lrow*C1S + lane]      * w2[lane]
                + c1s[lrow*C1S + 32 + lane] * w2[32 + lane];
        #pragma unroll
        for (int o = 16; o; o >>= 1) s += __shfl_xor_sync(0xffffffffu, s, o);
        if (lane == 0) clsOut[bm + lrow] = sigmoidf_(s + b2[0]);
    }
}

// ======================= fused GH GEMM + register GRU (t>=1) =================
#define GH_A64  (64*SRW2)              /* 2560 ushorts */
#define GH_B384 (384*SRW2)             /* 15360 ushorts */
#define GH_STG2 (2*GH_A64 + 2*GH_B384) /* 35840 ushorts */
#define GH_SMEM (2*GH_STG2*2)          /* 143360 B */

__global__ void __launch_bounds__(512, 1) ghgru_kernel(
    int t, const float* __restrict__ b_hh)
{
    extern __shared__ ushort_t smem[];
    uint32_t smem_b;
    asm("{ .reg .u64 t; cvta.to.shared.u64 t, %1; cvt.u32.u64 %0, t; }"
        : "=r"(smem_b) : "l"(smem));

    const int tid  = threadIdx.x;
    const int lane = tid & 31;
    const int w    = tid >> 5;
    const int gid  = lane >> 2;
    const int tig  = lane & 3;
    const int wm   = w >> 2;
    const int wn   = w & 3;
    const int bm   = blockIdx.x * 64;

    float acc[3][4][4];
    #pragma unroll
    for (int g = 0; g < 3; g++)
        #pragma unroll
        for (int j = 0; j < 4; j++)
            #pragma unroll
            for (int k = 0; k < 4; k++) acc[g][j][k] = 0.f;

    auto issue_copy = [&](int kc) {
        const uint32_t sb = smem_b + (uint32_t)((kc & 1) * GH_STG2) * 2u;
        // A: 64 rows x 4 segs x 2 arrays = 512 -> 1/thread
        {
            int arr = tid >> 8;              // 0=hi 1=lo
            int i   = tid & 255;
            int row = i >> 2, seg = i & 3;
            uint32_t soff = (uint32_t)(arr * GH_A64 + row * SRW2 + seg * 8) * 2u;
            int grow = bm + row;
            const ushort_t* src = (arr ? g_Hlo : g_Hhi)
                                + (size_t)min(grow, NNODES - 1) * 128 + kc * 32 + seg * 8;
            CP_ASYNC16(sb + soff, src, (grow < NNODES) ? 16 : 0);
        }
        // B: 384 rows x 4 segs x 2 arrays = 3072 -> 6/thread
        #pragma unroll
        for (int h = 0; h < 6; h++) {
            int i   = tid + h * 512;
            int arr = i >= 1536;
            int j   = arr ? i - 1536 : i;
            int row = j >> 2, seg = j & 3;
            uint32_t soff = (uint32_t)(2*GH_A64 + arr * GH_B384 + row * SRW2 + seg * 8) * 2u;
            const ushort_t* src = (arr ? g_Whhlo : g_Whhhi)
                                + (size_t)row * 128 + kc * 32 + seg * 8;
            CP_ASYNC16(sb + soff, src, 16);
        }
        CP_COMMIT();
    };

    issue_copy(0);
    for (int kc = 0; kc < 4; kc++) {
        if (kc + 1 < 4) { issue_copy(kc + 1); CP_WAIT1(); } else { CP_WAIT0(); }
        __syncthreads();
        const ushort_t* Ahi = smem + (kc & 1) * GH_STG2;
        const ushort_t* Alo = Ahi + GH_A64;
        const ushort_t* Bhi = Ahi + 2*GH_A64;
        const ushort_t* Blo = Bhi + GH_B384;
        #pragma unroll
        for (int ks = 0; ks < 2; ks++) {
            const int kk = ks*16 + tig*2;
            uint32_t afh[4], afl[4];
            LD_A4(afh, Ahi, SRW2, wm*16 + gid, kk);
            LD_A4(afl, Alo, SRW2, wm*16 + gid, kk);
            #pragma unroll
            for (int g = 0; g < 3; g++) {
                #pragma unroll
                for (int nt = 0; nt < 4; nt++) {
                    int cb = g*128 + wn*32 + nt*8 + gid;
                    uint32_t bfh[2], bfl[2];
                    LD_B2(bfh, Bhi, SRW2, cb, kk);
                    LD_B2(bfl, Blo, SRW2, cb, kk);
                    MMA_BF16(acc[g][nt], afh, bfh);
                    MMA_BF16(acc[g][nt], afh, bfl);
                    MMA_BF16(acc[g][nt], afl, bfh);
                }
            }
        }
        __syncthreads();
    }

    #pragma unroll
    for (int nt = 0; nt < 4; nt++) {
        int col = wn*32 + nt*8 + 2*tig;
        float2 bhr = *(const float2*)(b_hh + col);
        float2 bhz = *(const float2*)(b_hh + 128 + col);
        float2 bhn = *(const float2*)(b_hh + 256 + col);
        #pragma unroll
        for (int half = 0; half < 2; half++) {
            int node = bm + wm*16 + gid + half*8;
            if (node >= NNODES) continue;
            size_t m = (size_t)node*8 + t;
            float2 gxr = *(const float2*)(g_GX + m*384 + col);
            float2 gxz = *(const float2*)(g_GX + m*384 + 128 + col);
            float2 gxn = *(const float2*)(g_GX + m*384 + 256 + col);
            float2 h   = *(const float2*)(g_H + (size_t)node*HH + col);
            float ghr0 = acc[0][nt][half*2+0] + bhr.x, ghr1 = acc[0][nt][half*2+1] + bhr.y;
            float ghz0 = acc[1][nt][half*2+0] + bhz.x, ghz1 = acc[1][nt][half*2+1] + bhz.y;
            float ghn0 = acc[2][nt][half*2+0] + bhn.x, ghn1 = acc[2][nt][half*2+1] + bhn.y;
            float r0 = sigmoidf_(gxr.x + ghr0), r1 = sigmoidf_(gxr.y + ghr1);
            float z0 = sigmoidf_(gxz.x + ghz0), z1 = sigmoidf_(gxz.y + ghz1);
            float n0 = tanhf(gxn.x + r0*ghn0),  n1 = tanhf(gxn.y + r1*ghn1);
            float2 hn;
            hn.x = (1.f - z0)*n0 + z0*h.x;
            hn.y = (1.f - z1)*n1 + z1*h.y;
            *(float2*)(g_H + (size_t)node*HH + col) = hn;
            uint32_t hi, lo;
            bsplit2(hn.x, hn.y, hi, lo);
            *(uint32_t*)&g_Hhi [(size_t)node*128 + col] = hi;
            *(uint32_t*)&g_Hlo [(size_t)node*128 + col] = lo;
            *(uint32_t*)&g_HShi[m*128 + col] = hi;
            *(uint32_t*)&g_HSlo[m*128 + col] = lo;
        }
    }
}

// ======================= launch ==============================================
extern "C" void kernel_launch(void* const* d_in, const int* in_sizes, int n_in,
                              void* d_out, int out_size)
{
    const float* x     = (const float*)d_in[0];
    const void*  ei    = d_in[1];
    const float* Wl    = (const float*)d_in[2];
    const float* bl    = (const float*)d_in[3];
    const float* Wr    = (const float*)d_in[4];
    const float* W_ih  = (const float*)d_in[5];
    const float* b_ih  = (const float*)d_in[6];
    const float* W_hh  = (const float*)d_in[7];
    const float* b_hh  = (const float*)d_in[8];
    const float* W_rec = (const float*)d_in[9];
    const float* b_rec = (const float*)d_in[10];
    const float* W_c1  = (const float*)d_in[11];
    const float* b_c1  = (const float*)d_in[12];
    const float* W_c2  = (const float*)d_in[13];
    const float* b_c2  = (const float*)d_in[14];

    float* out      = (float*)d_out;
    float* outRecon = out;
    float* outCls   = out + (size_t)MROWS * COUT;

    cudaFuncSetAttribute(spgx_kernel,  cudaFuncAttributeMaxDynamicSharedMemorySize, SPX_SMEM);
    cudaFuncSetAttribute(head_kernel,  cudaFuncAttributeMaxDynamicSharedMemorySize, HEAD_SMEM);
    cudaFuncSetAttribute(ghgru_kernel, cudaFuncAttributeMaxDynamicSharedMemorySize, GH_SMEM);

    // graph + weight prep
    detect_kernel<<<1, 1>>>(ei);
    convert_kernel<<<(EDGES + 255)/256, 256>>>(ei);
    zero_kernel<<<256, 256>>>();
    wcat2_kernel<<<(128*64 + 255)/256, 256>>>(Wl, Wr);
    wih2_kernel<<<(384*128 + 255)/256, 256>>>(W_ih);
    whh2_kernel<<<(384*128 + 255)/256, 256>>>(W_hh);
    whd2_kernel<<<(96*128 + 255)/256, 256>>>(W_rec, b_rec, W_c1, b_c1);
    count_kernel<<<(EDGES + 255)/256, 256>>>();
    scan_kernel<<<1, 1024>>>();
    fill_kernel<<<(EDGES + 255)/256, 256>>>();
    gather_kernel<<<NNODES, 256>>>(x);

    // fused SP+GX
    spgx_kernel<<<MROWS/128, 512, SPX_SMEM>>>(bl, b_ih);

    // recurrence
    gru0_kernel<<<(NNODES*HH + 255)/256, 256>>>(b_hh);
    for (int t = 1; t < TT; t++)
        ghgru_kernel<<<(NNODES + 63)/64, 512, GH_SMEM>>>(t, b_hh);

    // heads
    head_kernel<<<MROWS/128, 512, HEAD_SMEM>>>(W_c2, b_c2, outRecon, outCls);
}